// round 2
// baseline (speedup 1.0000x reference)
#include <cuda_runtime.h>
#include <math.h>

// ---------------------------------------------------------------------------
// DIN: attention (factored) + MLP, fp32 with packed f32x2 FMA.
// combined[b] = [user_emb(32) | cand(64) | att(64)] -> MLP 160->256->128->1
// ---------------------------------------------------------------------------

#define GA 8          // batches per CTA in attention kernel
#define TMB 32        // rows per CTA in MLP kernel
#define NB 16384

__device__ float g_comb[NB * 160];

__device__ __forceinline__ unsigned long long pack2(float a, float b) {
    unsigned long long r;
    asm("mov.b64 %0, {%1, %2};" : "=l"(r) : "f"(a), "f"(b));
    return r;
}
__device__ __forceinline__ unsigned long long ffma2(unsigned long long a,
                                                    unsigned long long b,
                                                    unsigned long long c) {
    unsigned long long d;
    asm("fma.rn.f32x2 %0, %1, %2, %3;" : "=l"(d) : "l"(a), "l"(b), "l"(c));
    return d;
}
__device__ __forceinline__ void unpack2(unsigned long long v, float& a, float& b) {
    asm("mov.b64 {%0, %1}, %2;" : "=f"(a), "=f"(b) : "l"(v));
}

// ---------------------------------------------------------------------------
// Kernel A: attention. One CTA handles GA=8 batch rows.
// smem (floats): sBC[64*96] sE[64*96] sM[64*96] sH[64*68] sQ[8*64] sR[8*96]
//                sW2[96] sScore[64] sWt[64]   => 24288 floats = 97152 B
// ---------------------------------------------------------------------------
__global__ __launch_bounds__(256, 2)
void din_attention_kernel(
    const int* __restrict__ customer_id,
    const int* __restrict__ cand_good,
    const int* __restrict__ cand_class,
    const int* __restrict__ hist_goods,
    const int* __restrict__ hist_classes,
    const float* __restrict__ user_table,
    const float* __restrict__ item_table,
    const float* __restrict__ cat_table,
    const float* __restrict__ aw1,
    const float* __restrict__ ab1,
    const float* __restrict__ aw2,
    const float* __restrict__ ab2)
{
    extern __shared__ float sm[];
    float* sBC    = sm;           // 6144
    float* sE     = sm + 6144;    // 6144
    float* sM     = sm + 12288;   // 6144 (first used as staging for A+C)
    float* sH     = sm + 18432;   // 64*68 = 4352
    float* sQ     = sm + 22784;   // 512
    float* sR     = sm + 23296;   // 768
    float* sW2    = sm + 24064;   // 96
    float* sScore = sm + 24160;   // 64
    float* sWt    = sm + 24224;   // 64

    const int tid  = threadIdx.x;
    const int warp = tid >> 5;
    const int lane = tid & 31;
    const int b0   = blockIdx.x * GA;

    // ---- Phase 1: stage transformed attention weights -----------------
    // aw1 blocks (each [64,80]): A=rows 0..63 (mult q), B=64..127 (h),
    // C=128..191 (q-h), E=192..255 (q*h).
    // sBC = B - C ; sE = E ; sM (temp) = A + C. Columns padded 80->96 w/ 0.
    for (int idx = tid; idx < 6144; idx += 256) {
        int k = idx / 96, j = idx - k * 96;
        float bc = 0.f, e = 0.f, ac = 0.f;
        if (j < 80) {
            float Av = aw1[k * 80 + j];
            float Bv = aw1[(64 + k) * 80 + j];
            float Cv = aw1[(128 + k) * 80 + j];
            float Ev = aw1[(192 + k) * 80 + j];
            bc = Bv - Cv; e = Ev; ac = Av + Cv;
        }
        sBC[idx] = bc; sE[idx] = e; sM[idx] = ac;
    }
    if (tid < 96) sW2[tid] = (tid < 80) ? aw2[tid] : 0.f;

    // cand embeddings (q) + write user_emb/cand into combined scratch
    for (int idx = tid; idx < GA * 64; idx += 256) {
        int g = idx >> 6, d = idx & 63;
        int b = b0 + g;
        float v = (d < 32) ? item_table[cand_good[b] * 32 + d]
                           : cat_table[cand_class[b] * 32 + (d - 32)];
        sQ[idx] = v;
        g_comb[b * 160 + 32 + d] = v;
    }
    for (int idx = tid; idx < GA * 32; idx += 256) {
        int g = idx >> 5, d = idx & 31;
        int b = b0 + g;
        g_comb[b * 160 + d] = user_table[customer_id[b] * 32 + d];
    }
    __syncthreads();

    // ---- Phase 2: r[g][j] = ab1[j] + sum_k q[g][k]*(A+C)[k][j] --------
    for (int idx = tid; idx < GA * 96; idx += 256) {
        int g = idx / 96, j = idx - g * 96;
        float v = 0.f;
        if (j < 80) {
            v = ab1[j];
            #pragma unroll 8
            for (int k = 0; k < 64; k++)
                v += sQ[g * 64 + k] * sM[k * 96 + j];
        }
        sR[idx] = v;
    }
    __syncthreads();

    const int lg = lane >> 3;          // 0..3 : row group within warp
    const int jg = lane & 7;           // 0..7 : column group within warp
    const int r0 = warp * 8 + lg * 2;  // two rows r0, r0+1 for this thread

    for (int g = 0; g < GA; g++) {
        const int b = b0 + g;

        // build M = BC + diag(q) * E  (overwrites A+C staging; phase2 done)
        for (int idx = tid; idx < 6144; idx += 256) {
            int k = idx / 96;
            sM[idx] = sBC[idx] + sQ[g * 64 + k] * sE[idx];
        }
        // gather history rows (padded to 64 rows of zeros)
        for (int idx = tid; idx < 4096; idx += 256) {
            int l = idx >> 6, d = idx & 63;
            float v = 0.f;
            if (l < 50) {
                v = (d < 32) ? item_table[hist_goods[b * 50 + l] * 32 + d]
                             : cat_table[hist_classes[b * 50 + l] * 32 + (d - 32)];
            }
            sH[l * 68 + d] = v;
        }
        __syncthreads();

        // ---- GEMV: out[l][j] = relu(sum_k H[l][k]*M[k][j] + r[j]) -----
        // warp handles 8 rows (l = warp*8..+7); thread: 2 rows x 4 cols,
        // looping over 3 column blocks of 32. Packed f32x2 FMAs.
        float sc0 = 0.f, sc1 = 0.f;
        #pragma unroll 1
        for (int jb = 0; jb < 3; jb++) {
            const int j = jb * 32 + jg * 4;
            ulonglong2 rr = *(const ulonglong2*)&sR[g * 96 + j];
            unsigned long long a00 = rr.x, a01 = rr.y;
            unsigned long long a10 = rr.x, a11 = rr.y;
            const float4* h0 = (const float4*)&sH[r0 * 68];
            const float4* h1 = (const float4*)&sH[(r0 + 1) * 68];
            #pragma unroll 4
            for (int kk = 0; kk < 16; kk++) {
                float4 x0 = h0[kk];
                float4 x1 = h1[kk];
                const float xc0[4] = {x0.x, x0.y, x0.z, x0.w};
                const float xc1[4] = {x1.x, x1.y, x1.z, x1.w};
                #pragma unroll
                for (int t = 0; t < 4; t++) {
                    ulonglong2 m = *(const ulonglong2*)&sM[(kk * 4 + t) * 96 + j];
                    unsigned long long xr0 = pack2(xc0[t], xc0[t]);
                    unsigned long long xr1 = pack2(xc1[t], xc1[t]);
                    a00 = ffma2(xr0, m.x, a00);
                    a01 = ffma2(xr0, m.y, a01);
                    a10 = ffma2(xr1, m.x, a10);
                    a11 = ffma2(xr1, m.y, a11);
                }
            }
            float w0 = sW2[j], w1 = sW2[j + 1], w2 = sW2[j + 2], w3 = sW2[j + 3];
            float v0, v1, v2, v3;
            unpack2(a00, v0, v1); unpack2(a01, v2, v3);
            sc0 += fmaxf(v0, 0.f) * w0 + fmaxf(v1, 0.f) * w1
                 + fmaxf(v2, 0.f) * w2 + fmaxf(v3, 0.f) * w3;
            unpack2(a10, v0, v1); unpack2(a11, v2, v3);
            sc1 += fmaxf(v0, 0.f) * w0 + fmaxf(v1, 0.f) * w1
                 + fmaxf(v2, 0.f) * w2 + fmaxf(v3, 0.f) * w3;
        }
        // reduce over the 8 column-group lanes
        #pragma unroll
        for (int o = 4; o > 0; o >>= 1) {
            sc0 += __shfl_down_sync(0xFFFFFFFFu, sc0, o, 8);
            sc1 += __shfl_down_sync(0xFFFFFFFFu, sc1, o, 8);
        }
        if (jg == 0) {
            float scs[2] = {sc0, sc1};
            #pragma unroll
            for (int i = 0; i < 2; i++) {
                int l = r0 + i;
                if (l < 50) {
                    float s = scs[i] + ab2[0];
                    if (hist_goods[b * 50 + l] == 0) s = -1e9f;
                    sScore[l] = s;
                }
            }
        }
        __syncthreads();

        // ---- masked softmax over L=50 (warp 0) ------------------------
        if (warp == 0) {
            float s0 = (lane < 50) ? sScore[lane] : -INFINITY;
            float s1 = (lane + 32 < 50) ? sScore[lane + 32] : -INFINITY;
            float mx = fmaxf(s0, s1);
            #pragma unroll
            for (int o = 16; o > 0; o >>= 1)
                mx = fmaxf(mx, __shfl_xor_sync(0xFFFFFFFFu, mx, o));
            float e0 = (lane < 50) ? expf(s0 - mx) : 0.f;
            float e1 = (lane + 32 < 50) ? expf(s1 - mx) : 0.f;
            float sum = e0 + e1;
            #pragma unroll
            for (int o = 16; o > 0; o >>= 1)
                sum += __shfl_xor_sync(0xFFFFFFFFu, sum, o);
            float inv = 1.f / sum;
            if (lane < 50) sWt[lane] = e0 * inv;
            if (lane + 32 < 50) sWt[lane + 32] = e1 * inv;
        }
        __syncthreads();

        // ---- weighted pooling: att[d] = sum_l w[l]*H[l][d] ------------
        if (tid < 64) {
            float a = 0.f;
            #pragma unroll 10
            for (int l = 0; l < 50; l++) a += sWt[l] * sH[l * 68 + tid];
            g_comb[b * 160 + 96 + tid] = a;
        }
        __syncthreads();   // protect sH/sM/sScore for next batch
    }
}

// ---------------------------------------------------------------------------
// Kernel B: fused MLP 160 -> 256 -> 128 -> 1. TMB=32 rows per CTA.
// smem (floats): sX[32*161]=5152, sW[32*260]=8320, sZ1[32*260]=8320, sW3[128]
//   total 21920 floats = 87680 B
// ---------------------------------------------------------------------------
__global__ __launch_bounds__(256, 2)
void din_mlp_kernel(const float* __restrict__ mw1, const float* __restrict__ mb1,
                    const float* __restrict__ mw2, const float* __restrict__ mb2,
                    const float* __restrict__ mw3, const float* __restrict__ mb3,
                    float* __restrict__ out)
{
    extern __shared__ float sm[];
    float* sX  = sm;            // 5152 (reused for z2, stride 132)
    float* sW  = sm + 5152;     // 8320
    float* sZ1 = sm + 13472;    // 8320
    float* sW3 = sm + 21792;    // 128

    const int tid = threadIdx.x;
    const int r   = tid >> 3;   // 0..31 row
    const int c0  = tid & 7;    // column group
    const int b0  = blockIdx.x * TMB;

    for (int idx = tid; idx < TMB * 160; idx += 256) {
        int rr = idx / 160, cc = idx - rr * 160;
        sX[rr * 161 + cc] = g_comb[(b0 + rr) * 160 + cc];
    }
    if (tid < 128) sW3[tid] = mw3[tid];
    __syncthreads();

    // ---- Layer 1: 160 -> 256, per thread 32 outputs (8 x float4) ------
    unsigned long long acc1[8][2];
    #pragma unroll
    for (int i = 0; i < 8; i++) {
        ulonglong2 bb = *(const ulonglong2*)&mb1[i * 32 + c0 * 4];
        acc1[i][0] = bb.x; acc1[i][1] = bb.y;
    }
    for (int ks = 0; ks < 160; ks += 32) {
        for (int idx = tid; idx < 32 * 256; idx += 256) {
            int kk = idx >> 8, cc = idx & 255;
            sW[kk * 260 + cc] = mw1[(ks + kk) * 256 + cc];
        }
        __syncthreads();
        #pragma unroll 4
        for (int kk = 0; kk < 32; kk++) {
            float x = sX[r * 161 + ks + kk];
            unsigned long long xr = pack2(x, x);
            #pragma unroll
            for (int i = 0; i < 8; i++) {
                ulonglong2 w = *(const ulonglong2*)&sW[kk * 260 + i * 32 + c0 * 4];
                acc1[i][0] = ffma2(xr, w.x, acc1[i][0]);
                acc1[i][1] = ffma2(xr, w.y, acc1[i][1]);
            }
        }
        __syncthreads();
    }
    #pragma unroll
    for (int i = 0; i < 8; i++) {
        float v0, v1, v2, v3;
        unpack2(acc1[i][0], v0, v1); unpack2(acc1[i][1], v2, v3);
        float4 z = make_float4(fmaxf(v0, 0.f), fmaxf(v1, 0.f),
                               fmaxf(v2, 0.f), fmaxf(v3, 0.f));
        *(float4*)&sZ1[r * 260 + i * 32 + c0 * 4] = z;
    }
    __syncthreads();

    // ---- Layer 2: 256 -> 128, per thread 16 outputs (4 x float4) ------
    unsigned long long acc2[4][2];
    #pragma unroll
    for (int i = 0; i < 4; i++) {
        ulonglong2 bb = *(const ulonglong2*)&mb2[i * 32 + c0 * 4];
        acc2[i][0] = bb.x; acc2[i][1] = bb.y;
    }
    for (int ks = 0; ks < 256; ks += 32) {
        for (int idx = tid; idx < 32 * 128; idx += 256) {
            int kk = idx >> 7, cc = idx & 127;
            sW[kk * 260 + cc] = mw2[(ks + kk) * 128 + cc];
        }
        __syncthreads();
        #pragma unroll 4
        for (int kk = 0; kk < 32; kk++) {
            float x = sZ1[r * 260 + ks + kk];
            unsigned long long xr = pack2(x, x);
            #pragma unroll
            for (int i = 0; i < 4; i++) {
                ulonglong2 w = *(const ulonglong2*)&sW[kk * 260 + i * 32 + c0 * 4];
                acc2[i][0] = ffma2(xr, w.x, acc2[i][0]);
                acc2[i][1] = ffma2(xr, w.y, acc2[i][1]);
            }
        }
        __syncthreads();
    }
    #pragma unroll
    for (int i = 0; i < 4; i++) {
        float v0, v1, v2, v3;
        unpack2(acc2[i][0], v0, v1); unpack2(acc2[i][1], v2, v3);
        float4 z = make_float4(fmaxf(v0, 0.f), fmaxf(v1, 0.f),
                               fmaxf(v2, 0.f), fmaxf(v3, 0.f));
        *(float4*)&sX[r * 132 + i * 32 + c0 * 4] = z;   // z2 into sX region
    }
    __syncthreads();

    // ---- Layer 3: 128 -> 1 --------------------------------------------
    if (tid < 32) {
        float a = mb3[0];
        #pragma unroll 8
        for (int k = 0; k < 128; k++) a += sX[tid * 132 + k] * sW3[k];
        out[b0 + tid] = a;
    }
}

// ---------------------------------------------------------------------------
extern "C" void kernel_launch(void* const* d_in, const int* in_sizes, int n_in,
                              void* d_out, int out_size) {
    const int*   customer_id  = (const int*)d_in[0];
    const int*   cand_good    = (const int*)d_in[1];
    const int*   cand_class   = (const int*)d_in[2];
    const int*   hist_goods   = (const int*)d_in[3];
    const int*   hist_classes = (const int*)d_in[4];
    const float* user_table   = (const float*)d_in[5];
    const float* item_table   = (const float*)d_in[6];
    const float* cat_table    = (const float*)d_in[7];
    const float* aw1 = (const float*)d_in[8];
    const float* ab1 = (const float*)d_in[9];
    const float* aw2 = (const float*)d_in[10];
    const float* ab2 = (const float*)d_in[11];
    const float* mw1 = (const float*)d_in[12];
    const float* mb1 = (const float*)d_in[13];
    const float* mw2 = (const float*)d_in[14];
    const float* mb2 = (const float*)d_in[15];
    const float* mw3 = (const float*)d_in[16];
    const float* mb3 = (const float*)d_in[17];

    const int smemA = 24288 * 4;
    const int smemB = 21920 * 4;
    cudaFuncSetAttribute(din_attention_kernel,
                         cudaFuncAttributeMaxDynamicSharedMemorySize, smemA);
    cudaFuncSetAttribute(din_mlp_kernel,
                         cudaFuncAttributeMaxDynamicSharedMemorySize, smemB);

    din_attention_kernel<<<NB / GA, 256, smemA>>>(
        customer_id, cand_good, cand_class, hist_goods, hist_classes,
        user_table, item_table, cat_table, aw1, ab1, aw2, ab2);

    din_mlp_kernel<<<NB / TMB, 256, smemB>>>(
        mw1, mb1, mw2, mb2, mw3, mb3, (float*)d_out);
}

// round 3
// speedup vs baseline: 1.2636x; 1.2636x over previous
#include <cuda_runtime.h>
#include <math.h>

#define GA 8
#define NB 16384

__device__ float g_comb[NB * 160];
__device__ float g_BC[6144];
__device__ float g_E[6144];
__device__ float g_AC[6144];
__device__ float g_W2[96];

__device__ __forceinline__ unsigned long long pack2(float a, float b) {
    unsigned long long r;
    asm("mov.b64 %0, {%1, %2};" : "=l"(r) : "f"(a), "f"(b));
    return r;
}
__device__ __forceinline__ unsigned long long ffma2(unsigned long long a,
                                                    unsigned long long b,
                                                    unsigned long long c) {
    unsigned long long d;
    asm("fma.rn.f32x2 %0, %1, %2, %3;" : "=l"(d) : "l"(a), "l"(b), "l"(c));
    return d;
}
__device__ __forceinline__ void unpack2(unsigned long long v, float& a, float& b) {
    asm("mov.b64 {%0, %1}, %2;" : "=f"(a), "=f"(b) : "l"(v));
}

// ---------------------------------------------------------------------------
// Prep: fold the 4 aw1 blocks into BC = B-C, E, AC = A+C (80->96 zero pad),
// and pad aw2 -> 96. One-time per launch, ~us.
// ---------------------------------------------------------------------------
__global__ void din_prep(const float* __restrict__ aw1,
                         const float* __restrict__ aw2) {
    int idx = blockIdx.x * 256 + threadIdx.x;
    if (idx < 6144) {
        int k = idx / 96, j = idx - k * 96;
        float bc = 0.f, e = 0.f, ac = 0.f;
        if (j < 80) {
            float A = aw1[k * 80 + j];
            float B = aw1[(64 + k) * 80 + j];
            float C = aw1[(128 + k) * 80 + j];
            float E = aw1[(192 + k) * 80 + j];
            bc = B - C; e = E; ac = A + C;
        }
        g_BC[idx] = bc; g_E[idx] = e; g_AC[idx] = ac;
    }
    if (blockIdx.x == 0 && threadIdx.x < 96)
        g_W2[threadIdx.x] = (threadIdx.x < 80) ? aw2[threadIdx.x] : 0.f;
}

// ---------------------------------------------------------------------------
// Kernel A: attention. GA=8 batches per CTA, smem = 48000 B -> 3 CTAs/SM.
// smem floats: sM[6144] sH[64*68] sQ[512] sR[768] sW2[96] sScore[64] sWt[64]
// ---------------------------------------------------------------------------
__global__ __launch_bounds__(256, 3)
void din_attention_kernel(
    const int* __restrict__ customer_id,
    const int* __restrict__ cand_good,
    const int* __restrict__ cand_class,
    const int* __restrict__ hist_goods,
    const int* __restrict__ hist_classes,
    const float* __restrict__ user_table,
    const float* __restrict__ item_table,
    const float* __restrict__ cat_table,
    const float* __restrict__ ab1,
    const float* __restrict__ ab2)
{
    extern __shared__ float sm[];
    float* sM     = sm;           // 6144
    float* sH     = sm + 6144;    // 4352 (64 rows, stride 68)
    float* sQ     = sm + 10496;   // 512
    float* sR     = sm + 11008;   // 768
    float* sW2    = sm + 11776;   // 96
    float* sScore = sm + 11872;   // 64
    float* sWt    = sm + 11936;   // 64

    const int tid  = threadIdx.x;
    const int warp = tid >> 5;
    const int lane = tid & 31;
    const int b0   = blockIdx.x * GA;

    // ---- Phase 1: q gather + combined[user|cand] writes ----------------
    for (int idx = tid; idx < GA * 64; idx += 256) {
        int g = idx >> 6, d = idx & 63;
        int b = b0 + g;
        float v = (d < 32) ? item_table[cand_good[b] * 32 + d]
                           : cat_table[cand_class[b] * 32 + (d - 32)];
        sQ[idx] = v;
        g_comb[b * 160 + 32 + d] = v;
    }
    for (int idx = tid; idx < GA * 32; idx += 256) {
        int g = idx >> 5, d = idx & 31;
        int b = b0 + g;
        g_comb[b * 160 + d] = user_table[customer_id[b] * 32 + d];
    }
    if (tid < 96) sW2[tid] = g_W2[tid];
    __syncthreads();

    // ---- Phase 2: r[g][j] = ab1[j] + sum_k q[g][k]*AC[k][j] ------------
    for (int idx = tid; idx < GA * 96; idx += 256) {
        int g = idx / 96, j = idx - g * 96;
        float v = 0.f;
        if (j < 80) {
            v = ab1[j];
            #pragma unroll 8
            for (int k = 0; k < 64; k++)
                v += sQ[g * 64 + k] * __ldg(&g_AC[k * 96 + j]);
        }
        sR[idx] = v;
    }

    const int lg = lane >> 3;          // 0..3 row group
    const int jg = lane & 7;           // 0..7 col group
    const int r0 = warp * 8 + lg * 2;  // rows r0, r0+1

    for (int g = 0; g < GA; g++) {
        const int b = b0 + g;

        // M = BC + diag(q) * E  (from L2-hot scratch)
        for (int idx = tid; idx < 6144; idx += 256) {
            int k = idx / 96;
            sM[idx] = __ldg(&g_BC[idx]) + sQ[g * 64 + k] * __ldg(&g_E[idx]);
        }
        // gather history (rows padded 50 -> 64 with zeros)
        for (int idx = tid; idx < 4096; idx += 256) {
            int l = idx >> 6, d = idx & 63;
            float v = 0.f;
            if (l < 50) {
                v = (d < 32) ? item_table[hist_goods[b * 50 + l] * 32 + d]
                             : cat_table[hist_classes[b * 50 + l] * 32 + (d - 32)];
            }
            sH[l * 68 + d] = v;
        }
        __syncthreads();

        // ---- GEMV: out[l][j] = relu(H @ M + r)[l][j]; score = out@w2 ---
        float sc0 = 0.f, sc1 = 0.f;
        #pragma unroll 1
        for (int jb = 0; jb < 3; jb++) {
            const int j = jb * 32 + jg * 4;
            ulonglong2 rr = *(const ulonglong2*)&sR[g * 96 + j];
            unsigned long long a00 = rr.x, a01 = rr.y;
            unsigned long long a10 = rr.x, a11 = rr.y;
            const float4* h0 = (const float4*)&sH[r0 * 68];
            const float4* h1 = (const float4*)&sH[(r0 + 1) * 68];
            #pragma unroll 4
            for (int kk = 0; kk < 16; kk++) {
                float4 x0 = h0[kk];
                float4 x1 = h1[kk];
                const float xc0[4] = {x0.x, x0.y, x0.z, x0.w};
                const float xc1[4] = {x1.x, x1.y, x1.z, x1.w};
                #pragma unroll
                for (int t = 0; t < 4; t++) {
                    ulonglong2 m = *(const ulonglong2*)&sM[(kk * 4 + t) * 96 + j];
                    unsigned long long xr0 = pack2(xc0[t], xc0[t]);
                    unsigned long long xr1 = pack2(xc1[t], xc1[t]);
                    a00 = ffma2(xr0, m.x, a00);
                    a01 = ffma2(xr0, m.y, a01);
                    a10 = ffma2(xr1, m.x, a10);
                    a11 = ffma2(xr1, m.y, a11);
                }
            }
            float w0 = sW2[j], w1 = sW2[j + 1], w2 = sW2[j + 2], w3 = sW2[j + 3];
            float v0, v1, v2, v3;
            unpack2(a00, v0, v1); unpack2(a01, v2, v3);
            sc0 += fmaxf(v0, 0.f) * w0 + fmaxf(v1, 0.f) * w1
                 + fmaxf(v2, 0.f) * w2 + fmaxf(v3, 0.f) * w3;
            unpack2(a10, v0, v1); unpack2(a11, v2, v3);
            sc1 += fmaxf(v0, 0.f) * w0 + fmaxf(v1, 0.f) * w1
                 + fmaxf(v2, 0.f) * w2 + fmaxf(v3, 0.f) * w3;
        }
        #pragma unroll
        for (int o = 4; o > 0; o >>= 1) {
            sc0 += __shfl_down_sync(0xFFFFFFFFu, sc0, o, 8);
            sc1 += __shfl_down_sync(0xFFFFFFFFu, sc1, o, 8);
        }
        if (jg == 0) {
            float scs[2] = {sc0, sc1};
            #pragma unroll
            for (int i = 0; i < 2; i++) {
                int l = r0 + i;
                if (l < 50) {
                    float s = scs[i] + ab2[0];
                    if (hist_goods[b * 50 + l] == 0) s = -1e9f;
                    sScore[l] = s;
                }
            }
        }
        __syncthreads();

        // ---- masked softmax (warp 0) ----------------------------------
        if (warp == 0) {
            float s0 = (lane < 50) ? sScore[lane] : -INFINITY;
            float s1 = (lane + 32 < 50) ? sScore[lane + 32] : -INFINITY;
            float mx = fmaxf(s0, s1);
            #pragma unroll
            for (int o = 16; o > 0; o >>= 1)
                mx = fmaxf(mx, __shfl_xor_sync(0xFFFFFFFFu, mx, o));
            float e0 = (lane < 50) ? expf(s0 - mx) : 0.f;
            float e1 = (lane + 32 < 50) ? expf(s1 - mx) : 0.f;
            float sum = e0 + e1;
            #pragma unroll
            for (int o = 16; o > 0; o >>= 1)
                sum += __shfl_xor_sync(0xFFFFFFFFu, sum, o);
            float inv = 1.f / sum;
            if (lane < 50) sWt[lane] = e0 * inv;
            if (lane + 32 < 50) sWt[lane + 32] = e1 * inv;
        }
        __syncthreads();

        // ---- pooling ---------------------------------------------------
        if (tid < 64) {
            float a = 0.f;
            #pragma unroll 10
            for (int l = 0; l < 50; l++) a += sWt[l] * sH[l * 68 + tid];
            g_comb[b * 160 + 96 + tid] = a;
        }
        __syncthreads();
    }
}

// ---------------------------------------------------------------------------
// Kernel B: MLP 160 -> 256 -> 128 -> 1. 32 rows/CTA, 256 thr, 3 CTAs/SM.
// Thread = 2 rows x 16 cols, interleaved cols (c0*4 + u*32) => conflict-free
// W loads, x4 broadcast reuse. Register-prefetched 16-k weight slabs.
// smem floats: sX[32*164]=5248  sW[16*260]=4160  sZ1[32*260]=8320  sW3[128]
//   total 17856 floats = 71424 B
// ---------------------------------------------------------------------------
__global__ __launch_bounds__(256, 3)
void din_mlp_kernel(const float* __restrict__ mw1, const float* __restrict__ mb1,
                    const float* __restrict__ mw2, const float* __restrict__ mb2,
                    const float* __restrict__ mw3, const float* __restrict__ mb3,
                    float* __restrict__ out)
{
    extern __shared__ float sm[];
    float* sX  = sm;            // 5248 (stride 164; z2 reuse stride 132)
    float* sW  = sm + 5248;     // 4160 (L1 stride 260, L2 stride 132)
    float* sZ1 = sm + 9408;     // 8320 (stride 260)
    float* sW3 = sm + 17728;    // 128

    const int tid = threadIdx.x;
    const int b0  = blockIdx.x * 32;

    // load X tile (float4, stride 164 keeps 16B alignment)
    for (int f = tid; f < 1280; f += 256) {
        int row = f / 40, c4 = f - row * 40;
        *(float4*)&sX[row * 164 + c4 * 4] =
            *(const float4*)&g_comb[(b0 + row) * 160 + c4 * 4];
    }
    if (tid < 128) sW3[tid] = mw3[tid];

    const int half = tid >> 7;      // col half
    const int t    = tid & 127;
    const int rp   = t >> 3;        // 0..15 -> rows 2rp, 2rp+1
    const int c0   = t & 7;
    const int r0   = rp * 2;
    const int jb1  = half * 128 + c0 * 4;   // + u*32, u<4 : 16 cols (L1)
    const int jb2  = half * 64  + c0 * 4;   // + u*32, u<2 : 8 cols  (L2)

    // ---- Layer 1: 160 -> 256 -------------------------------------------
    unsigned long long acc1[2][8];
    #pragma unroll
    for (int u = 0; u < 4; u++) {
        ulonglong2 bb = *(const ulonglong2*)&mb1[jb1 + u * 32];
        acc1[0][2*u] = bb.x; acc1[0][2*u+1] = bb.y;
        acc1[1][2*u] = bb.x; acc1[1][2*u+1] = bb.y;
    }
    float4 pf[4];
    #pragma unroll
    for (int i = 0; i < 4; i++)
        pf[i] = *(const float4*)&mw1[tid * 4 + i * 1024];

    for (int s = 0; s < 10; s++) {
        #pragma unroll
        for (int i = 0; i < 4; i++) {
            int o = tid * 4 + i * 1024;
            *(float4*)&sW[(o >> 8) * 260 + (o & 255)] = pf[i];
        }
        __syncthreads();
        if (s < 9) {
            const float* src = mw1 + (s + 1) * 4096;
            #pragma unroll
            for (int i = 0; i < 4; i++)
                pf[i] = *(const float4*)&src[tid * 4 + i * 1024];
        }
        const int xb = s * 16;
        #pragma unroll 4
        for (int kk = 0; kk < 16; kk++) {
            float x0 = sX[r0 * 164 + xb + kk];
            float x1 = sX[(r0 + 1) * 164 + xb + kk];
            unsigned long long xr0 = pack2(x0, x0);
            unsigned long long xr1 = pack2(x1, x1);
            #pragma unroll
            for (int u = 0; u < 4; u++) {
                ulonglong2 w = *(const ulonglong2*)&sW[kk * 260 + jb1 + u * 32];
                acc1[0][2*u]   = ffma2(xr0, w.x, acc1[0][2*u]);
                acc1[0][2*u+1] = ffma2(xr0, w.y, acc1[0][2*u+1]);
                acc1[1][2*u]   = ffma2(xr1, w.x, acc1[1][2*u]);
                acc1[1][2*u+1] = ffma2(xr1, w.y, acc1[1][2*u+1]);
            }
        }
        __syncthreads();
    }
    #pragma unroll
    for (int r = 0; r < 2; r++)
        #pragma unroll
        for (int u = 0; u < 4; u++) {
            float v0, v1, v2, v3;
            unpack2(acc1[r][2*u], v0, v1); unpack2(acc1[r][2*u+1], v2, v3);
            float4 z = make_float4(fmaxf(v0, 0.f), fmaxf(v1, 0.f),
                                   fmaxf(v2, 0.f), fmaxf(v3, 0.f));
            *(float4*)&sZ1[(r0 + r) * 260 + jb1 + u * 32] = z;
        }

    // ---- Layer 2: 256 -> 128 -------------------------------------------
    unsigned long long acc2[2][4];
    #pragma unroll
    for (int u = 0; u < 2; u++) {
        ulonglong2 bb = *(const ulonglong2*)&mb2[jb2 + u * 32];
        acc2[0][2*u] = bb.x; acc2[0][2*u+1] = bb.y;
        acc2[1][2*u] = bb.x; acc2[1][2*u+1] = bb.y;
    }
    float4 pg[2];
    #pragma unroll
    for (int i = 0; i < 2; i++)
        pg[i] = *(const float4*)&mw2[tid * 4 + i * 1024];

    for (int s = 0; s < 16; s++) {
        #pragma unroll
        for (int i = 0; i < 2; i++) {
            int o = tid * 4 + i * 1024;
            *(float4*)&sW[(o >> 7) * 132 + (o & 127)] = pg[i];
        }
        __syncthreads();           // also covers z1 stores on s=0
        if (s < 15) {
            const float* src = mw2 + (s + 1) * 2048;
            #pragma unroll
            for (int i = 0; i < 2; i++)
                pg[i] = *(const float4*)&src[tid * 4 + i * 1024];
        }
        const int xb = s * 16;
        #pragma unroll 4
        for (int kk = 0; kk < 16; kk++) {
            float x0 = sZ1[r0 * 260 + xb + kk];
            float x1 = sZ1[(r0 + 1) * 260 + xb + kk];
            unsigned long long xr0 = pack2(x0, x0);
            unsigned long long xr1 = pack2(x1, x1);
            #pragma unroll
            for (int u = 0; u < 2; u++) {
                ulonglong2 w = *(const ulonglong2*)&sW[kk * 132 + jb2 + u * 32];
                acc2[0][2*u]   = ffma2(xr0, w.x, acc2[0][2*u]);
                acc2[0][2*u+1] = ffma2(xr0, w.y, acc2[0][2*u+1]);
                acc2[1][2*u]   = ffma2(xr1, w.x, acc2[1][2*u]);
                acc2[1][2*u+1] = ffma2(xr1, w.y, acc2[1][2*u+1]);
            }
        }
        __syncthreads();
    }
    #pragma unroll
    for (int r = 0; r < 2; r++)
        #pragma unroll
        for (int u = 0; u < 2; u++) {
            float v0, v1, v2, v3;
            unpack2(acc2[r][2*u], v0, v1); unpack2(acc2[r][2*u+1], v2, v3);
            float4 z = make_float4(fmaxf(v0, 0.f), fmaxf(v1, 0.f),
                                   fmaxf(v2, 0.f), fmaxf(v3, 0.f));
            *(float4*)&sX[(r0 + r) * 132 + jb2 + u * 32] = z;  // z2 reuse
        }
    __syncthreads();

    // ---- Layer 3: 128 -> 1 ---------------------------------------------
    {
        int row = tid >> 3, seg = tid & 7;
        float p = 0.f;
        #pragma unroll
        for (int k = seg * 16; k < seg * 16 + 16; k++)
            p += sX[row * 132 + k] * sW3[k];
        #pragma unroll
        for (int o = 4; o > 0; o >>= 1)
            p += __shfl_down_sync(0xFFFFFFFFu, p, o, 8);
        if (seg == 0) out[b0 + row] = p + mb3[0];
    }
}

// ---------------------------------------------------------------------------
extern "C" void kernel_launch(void* const* d_in, const int* in_sizes, int n_in,
                              void* d_out, int out_size) {
    const int*   customer_id  = (const int*)d_in[0];
    const int*   cand_good    = (const int*)d_in[1];
    const int*   cand_class   = (const int*)d_in[2];
    const int*   hist_goods   = (const int*)d_in[3];
    const int*   hist_classes = (const int*)d_in[4];
    const float* user_table   = (const float*)d_in[5];
    const float* item_table   = (const float*)d_in[6];
    const float* cat_table    = (const float*)d_in[7];
    const float* aw1 = (const float*)d_in[8];
    const float* ab1 = (const float*)d_in[9];
    const float* aw2 = (const float*)d_in[10];
    const float* ab2 = (const float*)d_in[11];
    const float* mw1 = (const float*)d_in[12];
    const float* mb1 = (const float*)d_in[13];
    const float* mw2 = (const float*)d_in[14];
    const float* mb2 = (const float*)d_in[15];
    const float* mw3 = (const float*)d_in[16];
    const float* mb3 = (const float*)d_in[17];

    const int smemA = 12000 * 4;
    const int smemB = 17856 * 4;
    cudaFuncSetAttribute(din_attention_kernel,
                         cudaFuncAttributeMaxDynamicSharedMemorySize, smemA);
    cudaFuncSetAttribute(din_mlp_kernel,
                         cudaFuncAttributeMaxDynamicSharedMemorySize, smemB);

    din_prep<<<24, 256>>>(aw1, aw2);

    din_attention_kernel<<<NB / GA, 256, smemA>>>(
        customer_id, cand_good, cand_class, hist_goods, hist_classes,
        user_table, item_table, cat_table, ab1, ab2);

    din_mlp_kernel<<<NB / 32, 256, smemB>>>(
        mw1, mb1, mw2, mb2, mw3, mb3, (float*)d_out);
}

// round 4
// speedup vs baseline: 1.7039x; 1.3485x over previous
#include <cuda_runtime.h>
#include <math.h>

#define GA 8
#define NB 16384
#define ROWS 56            // 7 GEMV warps x 8 rows (50 real + 6 zero pad)

__device__ float g_comb[NB * 160];
__device__ float g_BC[6144];
__device__ float g_E[6144];
__device__ float g_AC[6144];
__device__ float g_W2[96];

__device__ __forceinline__ unsigned long long pack2(float a, float b) {
    unsigned long long r;
    asm("mov.b64 %0, {%1, %2};" : "=l"(r) : "f"(a), "f"(b));
    return r;
}
__device__ __forceinline__ unsigned long long ffma2(unsigned long long a,
                                                    unsigned long long b,
                                                    unsigned long long c) {
    unsigned long long d;
    asm("fma.rn.f32x2 %0, %1, %2, %3;" : "=l"(d) : "l"(a), "l"(b), "l"(c));
    return d;
}
__device__ __forceinline__ void unpack2(unsigned long long v, float& a, float& b) {
    asm("mov.b64 {%0, %1}, %2;" : "=f"(a), "=f"(b) : "l"(v));
}
__device__ __forceinline__ void cp_async16(float* smem_dst, const float* gsrc) {
    unsigned s = (unsigned)__cvta_generic_to_shared(smem_dst);
    asm volatile("cp.async.cg.shared.global [%0], [%1], 16;" :: "r"(s), "l"(gsrc));
}
__device__ __forceinline__ void cp_async_commit() {
    asm volatile("cp.async.commit_group;");
}
__device__ __forceinline__ void cp_async_wait_all() {
    asm volatile("cp.async.wait_group 0;" ::: "memory");
}

// ---------------------------------------------------------------------------
// Prep: fold aw1 blocks: BC=B-C, E, AC=A+C (cols padded 80->96), pad aw2.
// ---------------------------------------------------------------------------
__global__ void din_prep(const float* __restrict__ aw1,
                         const float* __restrict__ aw2) {
    int idx = blockIdx.x * 256 + threadIdx.x;
    if (idx < 6144) {
        int k = idx / 96, j = idx - k * 96;
        float bc = 0.f, e = 0.f, ac = 0.f;
        if (j < 80) {
            float A = aw1[k * 80 + j];
            float B = aw1[(64 + k) * 80 + j];
            float C = aw1[(128 + k) * 80 + j];
            float E = aw1[(192 + k) * 80 + j];
            bc = B - C; e = E; ac = A + C;
        }
        g_BC[idx] = bc; g_E[idx] = e; g_AC[idx] = ac;
    }
    if (blockIdx.x == 0 && threadIdx.x < 96)
        g_W2[threadIdx.x] = (threadIdx.x < 80) ? aw2[threadIdx.x] : 0.f;
}

// ---------------------------------------------------------------------------
// Attention. GA=8 batches/CTA, 256 thr, 3 CTAs/SM.
// smem floats: sM 6144 | sH0 3808 | sH1 3808 | sQ 512 | sR 768 | sW2 96
//              sScore 64 | sWt 64  => 15264 floats = 61056 B
// ---------------------------------------------------------------------------
__global__ __launch_bounds__(256, 3)
void din_attention_kernel(
    const int* __restrict__ customer_id,
    const int* __restrict__ cand_good,
    const int* __restrict__ cand_class,
    const int* __restrict__ hist_goods,
    const int* __restrict__ hist_classes,
    const float* __restrict__ user_table,
    const float* __restrict__ item_table,
    const float* __restrict__ cat_table,
    const float* __restrict__ ab1,
    const float* __restrict__ ab2)
{
    extern __shared__ float sm[];
    float* sM     = sm;            // 6144
    float* sH0    = sm + 6144;     // 3808 (56 rows, stride 68)
    float* sH1    = sm + 9952;     // 3808
    float* sQ     = sm + 13760;    // 512
    float* sR     = sm + 14272;    // 768
    float* sW2    = sm + 15040;    // 96
    float* sScore = sm + 15136;    // 64
    float* sWt    = sm + 15200;    // 64

    const int tid  = threadIdx.x;
    const int warp = tid >> 5;
    const int lane = tid & 31;
    const int lg   = lane >> 3;
    const int jg   = lane & 7;
    const int b0   = blockIdx.x * GA;
    const float ab2v = __ldg(ab2);

    // ---- issue H(0) prefetch immediately (cp.async, 800 float4 total) ----
    {
        const int b = b0;
        #pragma unroll
        for (int i = 0; i < 4; i++) {
            int f4 = tid + 256 * i;
            if (f4 < 800) {
                int l = f4 >> 4, q4 = f4 & 15, d0 = q4 * 4;
                const float* src;
                if (d0 < 32) src = item_table + hist_goods[b * 50 + l] * 32 + d0;
                else         src = cat_table  + hist_classes[b * 50 + l] * 32 + (d0 - 32);
                cp_async16(&sH0[l * 68 + d0], src);
            }
        }
        cp_async_commit();
    }

    // zero pad rows 50..55 of both H buffers (done once; never overwritten)
    for (int idx = tid; idx < 384; idx += 256) {
        int l = 50 + (idx >> 6), d = idx & 63;
        sH0[l * 68 + d] = 0.f;
        sH1[l * 68 + d] = 0.f;
    }
    if (tid < 96) sW2[tid] = g_W2[tid];

    // q gather + combined[user|cand]
    for (int idx = tid; idx < GA * 64; idx += 256) {
        int g = idx >> 6, d = idx & 63;
        int b = b0 + g;
        float v = (d < 32) ? item_table[cand_good[b] * 32 + d]
                           : cat_table[cand_class[b] * 32 + (d - 32)];
        sQ[idx] = v;
        g_comb[b * 160 + 32 + d] = v;
    }
    for (int idx = tid; idx < GA * 32; idx += 256) {
        int g = idx >> 5, d = idx & 31;
        int b = b0 + g;
        g_comb[b * 160 + d] = user_table[customer_id[b] * 32 + d];
    }

    // stage AC into sM for the r-vector pass
    #pragma unroll
    for (int i = 0; i < 6; i++) {
        int f4 = tid + 256 * i;
        *(float4*)&sM[f4 * 4] = __ldg((const float4*)&g_AC[f4 * 4]);
    }
    __syncthreads();

    // r[g][j] = ab1[j] + sum_k q[g][k]*AC[k][j]
    #pragma unroll
    for (int i = 0; i < 3; i++) {
        int idx = tid + 256 * i;
        int g = idx / 96, j = idx - g * 96;
        float v = 0.f;
        if (j < 80) {
            v = __ldg(&ab1[j]);
            #pragma unroll 8
            for (int k = 0; k < 64; k++)
                v += sQ[g * 64 + k] * sM[k * 96 + j];
        }
        sR[idx] = v;
    }
    __syncthreads();   // AC reads done -> sM reusable

    // build M(0) = BC + diag(q0)*E
    #pragma unroll
    for (int i = 0; i < 6; i++) {
        int f4 = tid + 256 * i;
        int k = f4 / 24;
        float q = sQ[k];
        float4 bc = __ldg((const float4*)&g_BC[f4 * 4]);
        float4 e  = __ldg((const float4*)&g_E[f4 * 4]);
        float4 m;
        m.x = bc.x + q * e.x; m.y = bc.y + q * e.y;
        m.z = bc.z + q * e.z; m.w = bc.w + q * e.w;
        *(float4*)&sM[f4 * 4] = m;
    }
    cp_async_wait_all();
    __syncthreads();

    const int r0 = warp * 8 + lg * 2;   // rows r0, r0+1 (warps 0..6)

    for (int g = 0; g < GA; g++) {
        const int b = b0 + g;
        float* sHc = (g & 1) ? sH1 : sH0;
        float* sHa = (g & 1) ? sH0 : sH1;

        // prefetch H(g+1) into alt buffer (async, consumed after sync3)
        if (g < 7) {
            const int bn = b + 1;
            #pragma unroll
            for (int i = 0; i < 4; i++) {
                int f4 = tid + 256 * i;
                if (f4 < 800) {
                    int l = f4 >> 4, q4 = f4 & 15, d0 = q4 * 4;
                    const float* src;
                    if (d0 < 32) src = item_table + hist_goods[bn * 50 + l] * 32 + d0;
                    else         src = cat_table  + hist_classes[bn * 50 + l] * 32 + (d0 - 32);
                    cp_async16(&sHa[l * 68 + d0], src);
                }
            }
            cp_async_commit();
        }

        // mask prefetch for this thread's two rows (epilogue use)
        int mk0 = 1, mk1 = 1;
        if (warp < 7 && jg == 0) {
            if (r0 < 50)     mk0 = hist_goods[b * 50 + r0];
            if (r0 + 1 < 50) mk1 = hist_goods[b * 50 + r0 + 1];
        }

        // ---- GEMV (warps 0..6): out[l][j]=relu(H@M + r); score=out@w2 ----
        if (warp < 7) {
            unsigned long long acc[3][4];
            #pragma unroll
            for (int jb = 0; jb < 3; jb++) {
                ulonglong2 rr = *(const ulonglong2*)&sR[g * 96 + jb * 32 + jg * 4];
                acc[jb][0] = rr.x; acc[jb][1] = rr.y;
                acc[jb][2] = rr.x; acc[jb][3] = rr.y;
            }
            const float4* h0 = (const float4*)&sHc[r0 * 68];
            const float4* h1 = (const float4*)&sHc[(r0 + 1) * 68];
            #pragma unroll 2
            for (int kk4 = 0; kk4 < 16; kk4++) {
                float4 x0 = h0[kk4];
                float4 x1 = h1[kk4];
                unsigned long long xr0[4], xr1[4];
                xr0[0] = pack2(x0.x, x0.x); xr0[1] = pack2(x0.y, x0.y);
                xr0[2] = pack2(x0.z, x0.z); xr0[3] = pack2(x0.w, x0.w);
                xr1[0] = pack2(x1.x, x1.x); xr1[1] = pack2(x1.y, x1.y);
                xr1[2] = pack2(x1.z, x1.z); xr1[3] = pack2(x1.w, x1.w);
                #pragma unroll
                for (int t = 0; t < 4; t++) {
                    const int k = kk4 * 4 + t;
                    #pragma unroll
                    for (int jb = 0; jb < 3; jb++) {
                        ulonglong2 m = *(const ulonglong2*)&sM[k * 96 + jb * 32 + jg * 4];
                        acc[jb][0] = ffma2(xr0[t], m.x, acc[jb][0]);
                        acc[jb][1] = ffma2(xr0[t], m.y, acc[jb][1]);
                        acc[jb][2] = ffma2(xr1[t], m.x, acc[jb][2]);
                        acc[jb][3] = ffma2(xr1[t], m.y, acc[jb][3]);
                    }
                }
            }
            float sc0 = 0.f, sc1 = 0.f;
            #pragma unroll
            for (int jb = 0; jb < 3; jb++) {
                const int j = jb * 32 + jg * 4;
                float w0 = sW2[j], w1 = sW2[j+1], w2 = sW2[j+2], w3 = sW2[j+3];
                float v0, v1, v2, v3;
                unpack2(acc[jb][0], v0, v1); unpack2(acc[jb][1], v2, v3);
                sc0 += fmaxf(v0,0.f)*w0 + fmaxf(v1,0.f)*w1
                     + fmaxf(v2,0.f)*w2 + fmaxf(v3,0.f)*w3;
                unpack2(acc[jb][2], v0, v1); unpack2(acc[jb][3], v2, v3);
                sc1 += fmaxf(v0,0.f)*w0 + fmaxf(v1,0.f)*w1
                     + fmaxf(v2,0.f)*w2 + fmaxf(v3,0.f)*w3;
            }
            #pragma unroll
            for (int o = 4; o > 0; o >>= 1) {
                sc0 += __shfl_down_sync(0xFFFFFFFFu, sc0, o, 8);
                sc1 += __shfl_down_sync(0xFFFFFFFFu, sc1, o, 8);
            }
            if (jg == 0) {
                if (r0 < 50)
                    sScore[r0] = (mk0 == 0) ? -1e9f : sc0 + ab2v;
                if (r0 + 1 < 50)
                    sScore[r0 + 1] = (mk1 == 0) ? -1e9f : sc1 + ab2v;
            }
        }
        __syncthreads();   // sync1: scores ready, sM free

        // softmax (warp 0) overlapped with M(g+1) build (all threads)
        if (warp == 0) {
            float s0 = (lane < 50) ? sScore[lane] : -INFINITY;
            float s1 = (lane + 32 < 50) ? sScore[lane + 32] : -INFINITY;
            float mx = fmaxf(s0, s1);
            #pragma unroll
            for (int o = 16; o > 0; o >>= 1)
                mx = fmaxf(mx, __shfl_xor_sync(0xFFFFFFFFu, mx, o));
            float e0 = (lane < 50) ? expf(s0 - mx) : 0.f;
            float e1 = (lane + 32 < 50) ? expf(s1 - mx) : 0.f;
            float sum = e0 + e1;
            #pragma unroll
            for (int o = 16; o > 0; o >>= 1)
                sum += __shfl_xor_sync(0xFFFFFFFFu, sum, o);
            float inv = 1.f / sum;
            if (lane < 50) sWt[lane] = e0 * inv;
            if (lane + 32 < 50) sWt[lane + 32] = e1 * inv;
        }
        if (g < 7) {
            #pragma unroll
            for (int i = 0; i < 6; i++) {
                int f4 = tid + 256 * i;
                int k = f4 / 24;
                float q = sQ[(g + 1) * 64 + k];
                float4 bc = __ldg((const float4*)&g_BC[f4 * 4]);
                float4 e  = __ldg((const float4*)&g_E[f4 * 4]);
                float4 m;
                m.x = bc.x + q * e.x; m.y = bc.y + q * e.y;
                m.z = bc.z + q * e.z; m.w = bc.w + q * e.w;
                *(float4*)&sM[f4 * 4] = m;
            }
        }
        __syncthreads();   // sync2: weights + M(g+1) ready

        // pooling (warps 6,7) reads current H
        if (tid >= 192) {
            int d = tid - 192;
            float a = 0.f;
            #pragma unroll 10
            for (int l = 0; l < 50; l++) a += sWt[l] * sHc[l * 68 + d];
            g_comb[b * 160 + 96 + d] = a;
        }
        if (g < 7) cp_async_wait_all();
        __syncthreads();   // sync3: pooling done, H(g+1) landed
    }
}

// ---------------------------------------------------------------------------
// MLP 160 -> 256 -> 128 -> 1 (unchanged from R2). 32 rows/CTA, 3 CTAs/SM.
// ---------------------------------------------------------------------------
__global__ __launch_bounds__(256, 3)
void din_mlp_kernel(const float* __restrict__ mw1, const float* __restrict__ mb1,
                    const float* __restrict__ mw2, const float* __restrict__ mb2,
                    const float* __restrict__ mw3, const float* __restrict__ mb3,
                    float* __restrict__ out)
{
    extern __shared__ float sm[];
    float* sX  = sm;            // 5248
    float* sW  = sm + 5248;     // 4160
    float* sZ1 = sm + 9408;     // 8320
    float* sW3 = sm + 17728;    // 128

    const int tid = threadIdx.x;
    const int b0  = blockIdx.x * 32;

    for (int f = tid; f < 1280; f += 256) {
        int row = f / 40, c4 = f - row * 40;
        *(float4*)&sX[row * 164 + c4 * 4] =
            *(const float4*)&g_comb[(b0 + row) * 160 + c4 * 4];
    }
    if (tid < 128) sW3[tid] = mw3[tid];

    const int half = tid >> 7;
    const int t    = tid & 127;
    const int rp   = t >> 3;
    const int c0   = t & 7;
    const int r0   = rp * 2;
    const int jb1  = half * 128 + c0 * 4;
    const int jb2  = half * 64  + c0 * 4;

    unsigned long long acc1[2][8];
    #pragma unroll
    for (int u = 0; u < 4; u++) {
        ulonglong2 bb = *(const ulonglong2*)&mb1[jb1 + u * 32];
        acc1[0][2*u] = bb.x; acc1[0][2*u+1] = bb.y;
        acc1[1][2*u] = bb.x; acc1[1][2*u+1] = bb.y;
    }
    float4 pf[4];
    #pragma unroll
    for (int i = 0; i < 4; i++)
        pf[i] = *(const float4*)&mw1[tid * 4 + i * 1024];

    for (int s = 0; s < 10; s++) {
        #pragma unroll
        for (int i = 0; i < 4; i++) {
            int o = tid * 4 + i * 1024;
            *(float4*)&sW[(o >> 8) * 260 + (o & 255)] = pf[i];
        }
        __syncthreads();
        if (s < 9) {
            const float* src = mw1 + (s + 1) * 4096;
            #pragma unroll
            for (int i = 0; i < 4; i++)
                pf[i] = *(const float4*)&src[tid * 4 + i * 1024];
        }
        const int xb = s * 16;
        #pragma unroll 4
        for (int kk = 0; kk < 16; kk++) {
            float x0 = sX[r0 * 164 + xb + kk];
            float x1 = sX[(r0 + 1) * 164 + xb + kk];
            unsigned long long xr0 = pack2(x0, x0);
            unsigned long long xr1 = pack2(x1, x1);
            #pragma unroll
            for (int u = 0; u < 4; u++) {
                ulonglong2 w = *(const ulonglong2*)&sW[kk * 260 + jb1 + u * 32];
                acc1[0][2*u]   = ffma2(xr0, w.x, acc1[0][2*u]);
                acc1[0][2*u+1] = ffma2(xr0, w.y, acc1[0][2*u+1]);
                acc1[1][2*u]   = ffma2(xr1, w.x, acc1[1][2*u]);
                acc1[1][2*u+1] = ffma2(xr1, w.y, acc1[1][2*u+1]);
            }
        }
        __syncthreads();
    }
    #pragma unroll
    for (int r = 0; r < 2; r++)
        #pragma unroll
        for (int u = 0; u < 4; u++) {
            float v0, v1, v2, v3;
            unpack2(acc1[r][2*u], v0, v1); unpack2(acc1[r][2*u+1], v2, v3);
            float4 z = make_float4(fmaxf(v0, 0.f), fmaxf(v1, 0.f),
                                   fmaxf(v2, 0.f), fmaxf(v3, 0.f));
            *(float4*)&sZ1[(r0 + r) * 260 + jb1 + u * 32] = z;
        }

    unsigned long long acc2[2][4];
    #pragma unroll
    for (int u = 0; u < 2; u++) {
        ulonglong2 bb = *(const ulonglong2*)&mb2[jb2 + u * 32];
        acc2[0][2*u] = bb.x; acc2[0][2*u+1] = bb.y;
        acc2[1][2*u] = bb.x; acc2[1][2*u+1] = bb.y;
    }
    float4 pg[2];
    #pragma unroll
    for (int i = 0; i < 2; i++)
        pg[i] = *(const float4*)&mw2[tid * 4 + i * 1024];

    for (int s = 0; s < 16; s++) {
        #pragma unroll
        for (int i = 0; i < 2; i++) {
            int o = tid * 4 + i * 1024;
            *(float4*)&sW[(o >> 7) * 132 + (o & 127)] = pg[i];
        }
        __syncthreads();
        if (s < 15) {
            const float* src = mw2 + (s + 1) * 2048;
            #pragma unroll
            for (int i = 0; i < 2; i++)
                pg[i] = *(const float4*)&src[tid * 4 + i * 1024];
        }
        const int xb = s * 16;
        #pragma unroll 4
        for (int kk = 0; kk < 16; kk++) {
            float x0 = sZ1[r0 * 260 + xb + kk];
            float x1 = sZ1[(r0 + 1) * 260 + xb + kk];
            unsigned long long xr0 = pack2(x0, x0);
            unsigned long long xr1 = pack2(x1, x1);
            #pragma unroll
            for (int u = 0; u < 2; u++) {
                ulonglong2 w = *(const ulonglong2*)&sW[kk * 132 + jb2 + u * 32];
                acc2[0][2*u]   = ffma2(xr0, w.x, acc2[0][2*u]);
                acc2[0][2*u+1] = ffma2(xr0, w.y, acc2[0][2*u+1]);
                acc2[1][2*u]   = ffma2(xr1, w.x, acc2[1][2*u]);
                acc2[1][2*u+1] = ffma2(xr1, w.y, acc2[1][2*u+1]);
            }
        }
        __syncthreads();
    }
    #pragma unroll
    for (int r = 0; r < 2; r++)
        #pragma unroll
        for (int u = 0; u < 2; u++) {
            float v0, v1, v2, v3;
            unpack2(acc2[r][2*u], v0, v1); unpack2(acc2[r][2*u+1], v2, v3);
            float4 z = make_float4(fmaxf(v0, 0.f), fmaxf(v1, 0.f),
                                   fmaxf(v2, 0.f), fmaxf(v3, 0.f));
            *(float4*)&sX[(r0 + r) * 132 + jb2 + u * 32] = z;
        }
    __syncthreads();

    {
        int row = tid >> 3, seg = tid & 7;
        float p = 0.f;
        #pragma unroll
        for (int k = seg * 16; k < seg * 16 + 16; k++)
            p += sX[row * 132 + k] * sW3[k];
        #pragma unroll
        for (int o = 4; o > 0; o >>= 1)
            p += __shfl_down_sync(0xFFFFFFFFu, p, o, 8);
        if (seg == 0) out[b0 + row] = p + mb3[0];
    }
}

// ---------------------------------------------------------------------------
extern "C" void kernel_launch(void* const* d_in, const int* in_sizes, int n_in,
                              void* d_out, int out_size) {
    const int*   customer_id  = (const int*)d_in[0];
    const int*   cand_good    = (const int*)d_in[1];
    const int*   cand_class   = (const int*)d_in[2];
    const int*   hist_goods   = (const int*)d_in[3];
    const int*   hist_classes = (const int*)d_in[4];
    const float* user_table   = (const float*)d_in[5];
    const float* item_table   = (const float*)d_in[6];
    const float* cat_table    = (const float*)d_in[7];
    const float* aw1 = (const float*)d_in[8];
    const float* ab1 = (const float*)d_in[9];
    const float* aw2 = (const float*)d_in[10];
    const float* ab2 = (const float*)d_in[11];
    const float* mw1 = (const float*)d_in[12];
    const float* mb1 = (const float*)d_in[13];
    const float* mw2 = (const float*)d_in[14];
    const float* mb2 = (const float*)d_in[15];
    const float* mw3 = (const float*)d_in[16];
    const float* mb3 = (const float*)d_in[17];

    const int smemA = 15264 * 4;
    const int smemB = 17856 * 4;
    cudaFuncSetAttribute(din_attention_kernel,
                         cudaFuncAttributeMaxDynamicSharedMemorySize, smemA);
    cudaFuncSetAttribute(din_mlp_kernel,
                         cudaFuncAttributeMaxDynamicSharedMemorySize, smemB);

    din_prep<<<24, 256>>>(aw1, aw2);

    din_attention_kernel<<<NB / GA, 256, smemA>>>(
        customer_id, cand_good, cand_class, hist_goods, hist_classes,
        user_table, item_table, cat_table, ab1, ab2);

    din_mlp_kernel<<<NB / 32, 256, smemB>>>(
        mw1, mb1, mw2, mb2, mw3, mb3, (float*)d_out);
}